// round 10
// baseline (speedup 1.0000x reference)
#include <cuda_runtime.h>
#include <cuda_bf16.h>
#include <cstdint>

#define D 512
#define HEADS 8
#define HD 64
#define TSEQ 1024
#define CHUNK 64
#define NC (TSEQ / CHUNK)   // 16
#define MAXB 4

// ---------------- scratch (no allocations allowed) ----------------
__device__ float g_q[MAXB * TSEQ * D];
__device__ float g_k[MAXB * TSEQ * D];
__device__ float g_v[MAXB * TSEQ * D];
__device__ float g_ckv[MAXB * HEADS * NC * HD * HD];
__device__ float g_cks[MAXB * HEADS * NC * HD];
// bf16 split operands
__device__ __nv_bfloat16 g_whi[4 * D * D];
__device__ __nv_bfloat16 g_wlo[4 * D * D];
__device__ __nv_bfloat16 g_xhi[MAXB * TSEQ * D];
__device__ __nv_bfloat16 g_xlo[MAXB * TSEQ * D];
__device__ __nv_bfloat16 g_phi[MAXB * TSEQ * D];   // post-attention activations
__device__ __nv_bfloat16 g_plo[MAXB * TSEQ * D];

// ---------------- helpers ----------------
__device__ __forceinline__ void split2(float f, uint16_t& h, uint16_t& l) {
    __nv_bfloat16 hb = __float2bfloat16_rn(f);
    float hf = __bfloat162float(hb);
    __nv_bfloat16 lb = __float2bfloat16_rn(f - hf);
    h = __bfloat16_as_ushort(hb);
    l = __bfloat16_as_ushort(lb);
}

__device__ __forceinline__ void mma_bf16(float* d, const uint32_t* a, const uint32_t* b) {
    asm volatile(
        "mma.sync.aligned.m16n8k16.row.col.f32.bf16.bf16.f32 "
        "{%0,%1,%2,%3}, {%4,%5,%6,%7}, {%8,%9}, {%0,%1,%2,%3};"
        : "+f"(d[0]), "+f"(d[1]), "+f"(d[2]), "+f"(d[3])
        : "r"(a[0]), "r"(a[1]), "r"(a[2]), "r"(a[3]), "r"(b[0]), "r"(b[1]));
}

__device__ __forceinline__ uint32_t smem_u32(const void* p) {
    uint32_t a;
    asm("{ .reg .u64 t; cvta.to.shared.u64 t, %1; cvt.u32.u64 %0, t; }"
        : "=r"(a) : "l"(p));
    return a;
}
__device__ __forceinline__ void cp16(uint32_t dst, const void* src) {
    asm volatile("cp.async.cg.shared.global [%0], [%1], 16;"
                 :: "r"(dst), "l"(src));
}
#define CP_COMMIT() asm volatile("cp.async.commit_group;" ::: "memory")
#define CP_WAIT(n)  asm volatile("cp.async.wait_group %0;" :: "n"(n) : "memory")

#define LDSM4(r, addr) \
    asm volatile("ldmatrix.sync.aligned.m8n8.x4.shared.b16 {%0,%1,%2,%3}, [%4];" \
        : "=r"((r)[0]), "=r"((r)[1]), "=r"((r)[2]), "=r"((r)[3]) : "r"(addr))

// ---------------- merged conversion kernel (weights + x) ----------------
#define W4 (4 * D * D / 4)      // 262144 float4s of weights
__global__ void __launch_bounds__(256) convert_all(
    const float* __restrict__ x,
    const float* __restrict__ Wq, const float* __restrict__ Wk,
    const float* __restrict__ Wv, const float* __restrict__ Wo, int n4x)
{
    int gid = blockIdx.x * 256 + threadIdx.x;
    if (gid < W4) {
        int w = gid >> 16;
        int off = gid & 65535;
        const float* src = (w == 0) ? Wq : (w == 1) ? Wk : (w == 2) ? Wv : Wo;
        float4 v = ((const float4*)src)[off];
        float f[4] = {v.x, v.y, v.z, v.w};
        uint16_t h[4], l[4];
#pragma unroll
        for (int j = 0; j < 4; ++j) split2(f[j], h[j], l[j]);
        ((uint2*)(g_whi + (size_t)w * D * D))[off] =
            make_uint2((uint32_t)h[0] | ((uint32_t)h[1] << 16),
                       (uint32_t)h[2] | ((uint32_t)h[3] << 16));
        ((uint2*)(g_wlo + (size_t)w * D * D))[off] =
            make_uint2((uint32_t)l[0] | ((uint32_t)l[1] << 16),
                       (uint32_t)l[2] | ((uint32_t)l[3] << 16));
    } else {
        int i = gid - W4;
        if (i < n4x) {
            float4 v = ((const float4*)x)[i];
            float f[4] = {v.x, v.y, v.z, v.w};
            uint16_t h[4], l[4];
#pragma unroll
            for (int j = 0; j < 4; ++j) split2(f[j], h[j], l[j]);
            ((uint2*)g_xhi)[i] = make_uint2((uint32_t)h[0] | ((uint32_t)h[1] << 16),
                                            (uint32_t)h[2] | ((uint32_t)h[3] << 16));
            ((uint2*)g_xlo)[i] = make_uint2((uint32_t)l[0] | ((uint32_t)l[1] << 16),
                                            (uint32_t)l[2] | ((uint32_t)l[3] << 16));
        }
    }
}

// ---------------- mma.sync split-bf16 GEMM (KC=32, 2 CTAs/SM) ----------------
// smem per buffer: AHI/ALO/BHI/BLO, 128 rows x (16 data + 4 pad) u32 = 40960 B.
// Row stride 80B = odd multiple of 16B -> ldmatrix conflict-free.
#define ROWU 20
#define ARRU (128 * ROWU)      // 2560
#define BUFU (4 * ARRU)        // 10240
#define GEMM_SMEM (2 * BUFU * 4)   // 81920 bytes -> 2 CTAs/SM

// async copy one K-chunk (32 elems = 16 u32 per row) into buffer at byte base sbB
__device__ __forceinline__ void load_chunk_async(
    uint32_t sbB, const uint32_t* Ahi, const uint32_t* Alo,
    const uint32_t* Bhi, const uint32_t* Blo,
    int rowBase, int colBase, int k0u, int tid)
{
#pragma unroll
    for (int it = 0; it < 2; ++it) {
        int lin = tid + it * 256;          // 0..511
        int r = lin >> 2, q = lin & 3;     // r 0..127, q 0..3 (16B each)
        uint32_t dOff = (uint32_t)(r * ROWU + q * 4) * 4;
        cp16(sbB + dOff, Ahi + (size_t)(rowBase + r) * 256 + k0u + q * 4);
        cp16(sbB + ARRU * 4 + dOff, Alo + (size_t)(rowBase + r) * 256 + k0u + q * 4);
        cp16(sbB + 2 * ARRU * 4 + dOff, Bhi + (size_t)(colBase + r) * 256 + k0u + q * 4);
        cp16(sbB + 3 * ARRU * 4 + dOff, Blo + (size_t)(colBase + r) * 256 + k0u + q * 4);
    }
}

__global__ void __launch_bounds__(256, 2) mma_gemm(
    int asel, int wBase, int oselBase,
    const float* __restrict__ bias0, const float* __restrict__ bias1,
    const float* __restrict__ bias2,
    float* __restrict__ Oext, int actmask)
{
    extern __shared__ __align__(16) uint32_t smu[];
    int tid = threadIdx.x, lane = tid & 31, wid = tid >> 5;
    int warpRow = wid >> 2;
    int warpCol = wid & 3;
    int z = blockIdx.z;
    int rowBase = blockIdx.y * 128;
    int colBase = blockIdx.x * 128;

    const uint32_t* Ahi = asel ? (const uint32_t*)g_phi : (const uint32_t*)g_xhi;
    const uint32_t* Alo = asel ? (const uint32_t*)g_plo : (const uint32_t*)g_xlo;
    int wz = wBase + z;
    const uint32_t* Bhi = (const uint32_t*)g_whi + (size_t)wz * (D * D / 2);
    const uint32_t* Blo = (const uint32_t*)g_wlo + (size_t)wz * (D * D / 2);
    const float* bias = (z == 0) ? bias0 : (z == 1) ? bias1 : bias2;
    int osel = oselBase + z;
    float* O = (osel == 3) ? Oext : (osel == 0 ? g_q : (osel == 1 ? g_k : g_v));
    int act = (actmask >> z) & 1;

    uint32_t sbB = smem_u32(smu);

    // ldmatrix lane addressing
    int lrA = lane & 15, lhA = lane >> 4;
    int brB = ((lane >> 4) << 3) + (lane & 7);
    int bhB = (lane >> 3) & 1;

    float acc[4][4][4];
#pragma unroll
    for (int mt = 0; mt < 4; ++mt)
#pragma unroll
        for (int nt = 0; nt < 4; ++nt)
#pragma unroll
            for (int r = 0; r < 4; ++r) acc[mt][nt][r] = 0.f;

    load_chunk_async(sbB, Ahi, Alo, Bhi, Blo, rowBase, colBase, 0, tid);
    CP_COMMIT();

    for (int c = 0; c < 16; ++c) {
        int buf = c & 1;
        if (c < 15) {
            load_chunk_async(sbB + ((c + 1) & 1) * BUFU * 4,
                             Ahi, Alo, Bhi, Blo, rowBase, colBase,
                             (c + 1) * 16, tid);
            CP_COMMIT();
            CP_WAIT(1);
        } else {
            CP_WAIT(0);
        }
        __syncthreads();

        uint32_t aBH = sbB + (uint32_t)buf * BUFU * 4;
        uint32_t aBL = aBH + ARRU * 4;
        uint32_t bBH = aBH + 2 * ARRU * 4;
        uint32_t bBL = aBH + 3 * ARRU * 4;
#pragma unroll
        for (int ks = 0; ks < 2; ++ks) {
            uint32_t ahi[4][4], alo[4][4];
#pragma unroll
            for (int mt = 0; mt < 4; ++mt) {
                uint32_t off = (uint32_t)((warpRow * 64 + mt * 16 + lrA) * ROWU
                                          + ks * 8 + lhA * 4) * 4;
                LDSM4(ahi[mt], aBH + off);
                LDSM4(alo[mt], aBL + off);
            }
#pragma unroll
            for (int p = 0; p < 2; ++p) {
                uint32_t off = (uint32_t)((warpCol * 32 + p * 16 + brB) * ROWU
                                          + ks * 8 + bhB * 4) * 4;
                uint32_t t0[4], t1[4];
                LDSM4(t0, bBH + off);
                LDSM4(t1, bBL + off);
#pragma unroll
                for (int mt = 0; mt < 4; ++mt)
#pragma unroll
                    for (int q = 0; q < 2; ++q) {
                        int nt = 2 * p + q;
                        mma_bf16(acc[mt][nt], ahi[mt], &t0[2 * q]);
                        mma_bf16(acc[mt][nt], ahi[mt], &t1[2 * q]);
                        mma_bf16(acc[mt][nt], alo[mt], &t0[2 * q]);
                    }
            }
        }
        __syncthreads();
    }

#pragma unroll
    for (int mt = 0; mt < 4; ++mt) {
        int r0 = rowBase + warpRow * 64 + mt * 16 + (lane >> 2);
#pragma unroll
        for (int nt = 0; nt < 4; ++nt) {
            int cc = colBase + warpCol * 32 + nt * 8 + (lane & 3) * 2;
            float b0 = bias[cc], b1 = bias[cc + 1];
            float v0 = acc[mt][nt][0] + b0;
            float v1 = acc[mt][nt][1] + b1;
            float v2 = acc[mt][nt][2] + b0;
            float v3 = acc[mt][nt][3] + b1;
            if (act) {
                v0 = (v0 > 0.f) ? v0 + 1.f : __expf(v0);
                v1 = (v1 > 0.f) ? v1 + 1.f : __expf(v1);
                v2 = (v2 > 0.f) ? v2 + 1.f : __expf(v2);
                v3 = (v3 > 0.f) ? v3 + 1.f : __expf(v3);
            }
            *(float2*)&O[(size_t)r0 * D + cc] = make_float2(v0, v1);
            *(float2*)&O[(size_t)(r0 + 8) * D + cc] = make_float2(v2, v3);
        }
    }
}

// ---------------- per-chunk local sums (CHUNK=64, m-split x2) ----------------
__global__ void __launch_bounds__(256) chunk_sum_kernel()
{
    int bc = blockIdx.x;            // b*NC + c
    int hm = blockIdx.y;
    int h = hm >> 1, mh = hm & 1;
    int b = bc / NC, c = bc % NC;
    extern __shared__ __align__(16) float smf[];
    float* ks = smf;                   // [CHUNK][HD]
    float* vs = smf + CHUNK * HD;      // [CHUNK][32]

    int tid = threadIdx.x;
    size_t nbase = (size_t)b * TSEQ + (size_t)c * CHUNK;

#pragma unroll
    for (int it = 0; it < 4; it++) {
        int lin = tid + it * 256;
        int t = lin >> 4;
        int d4 = lin & 15;
        ((float4*)ks)[lin] = *(const float4*)&g_k[(nbase + t) * D + h * HD + d4 * 4];
    }
#pragma unroll
    for (int it = 0; it < 2; it++) {
        int lin = tid + it * 256;
        int t = lin >> 3;
        int m4 = lin & 7;
        ((float4*)vs)[lin] =
            *(const float4*)&g_v[(nbase + t) * D + h * HD + mh * 32 + m4 * 4];
    }
    __syncthreads();

    int d0 = (tid >> 4) * 4;
    int m0 = (tid & 15) * 2;
    float acc[4][2];
#pragma unroll
    for (int i = 0; i < 4; i++) { acc[i][0] = 0.f; acc[i][1] = 0.f; }

#pragma unroll 8
    for (int t = 0; t < CHUNK; t++) {
        float4 kd = *(const float4*)&ks[t * HD + d0];
        float2 vm = *(const float2*)&vs[t * 32 + m0];
        float ka[4] = {kd.x, kd.y, kd.z, kd.w};
#pragma unroll
        for (int i = 0; i < 4; i++) {
            acc[i][0] += ka[i] * vm.x;
            acc[i][1] += ka[i] * vm.y;
        }
    }

    size_t sidx = ((size_t)(b * HEADS + h) * NC + c);
    float* ckv = g_ckv + sidx * HD * HD;
#pragma unroll
    for (int i = 0; i < 4; i++)
        *(float2*)&ckv[(d0 + i) * HD + mh * 32 + m0] = make_float2(acc[i][0], acc[i][1]);

    if (mh == 0 && tid < HD) {
        float s = 0.f;
#pragma unroll 8
        for (int t = 0; t < CHUNK; t++) s += ks[t * HD + tid];
        g_cks[sidx * HD + tid] = s;
    }
}
#define CS_SMEM ((CHUNK * HD + CHUNK * 32) * 4)   // 24576 B

// ---------------- exclusive prefix over chunks per (b,h) ----------------
__global__ void __launch_bounds__(256) prefix_kernel()
{
    int bh = blockIdx.x;
    int tid = threadIdx.x;
    float* base = g_ckv + (size_t)bh * NC * HD * HD;
    for (int e = tid; e < HD * HD; e += 256) {
        float carry = 0.f;
#pragma unroll
        for (int c = 0; c < NC; c++) {
            float tv = base[c * HD * HD + e];
            base[c * HD * HD + e] = carry;
            carry += tv;
        }
    }
    if (tid < HD) {
        float* kb = g_cks + (size_t)bh * NC * HD;
        float carry = 0.f;
#pragma unroll
        for (int c = 0; c < NC; c++) {
            float tv = kb[c * HD + tid];
            kb[c * HD + tid] = carry;
            carry += tv;
        }
    }
}

// ---------------- per-chunk attention (CHUNK=64) ----------------
#define SP 68
#define QT_OFF 0
#define KT_OFF (HD * SP)                 // 4352
#define V_OFF  (KT_OFF + HD * SP)        // 8704
#define S_OFF  (V_OFF + CHUNK * SP)      // 13056
#define KVP_OFF (S_OFF + CHUNK * SP)     // 17408
#define KS_OFF (KVP_OFF + HD * SP)       // 21760
#define DN_OFF (KS_OFF + HD)             // 21824
#define SM2C_FLOATS (DN_OFF + CHUNK)     // 21888 floats = 87552 B

__global__ void __launch_bounds__(256) attn_chunk_kernel()
{
    int bc = blockIdx.x;
    int h = blockIdx.y;
    int b = bc / NC, c = bc % NC;
    extern __shared__ __align__(16) float smf[];
    float* Qt = smf + QT_OFF;
    float* Kt = smf + KT_OFF;
    float* V  = smf + V_OFF;
    float* S  = smf + S_OFF;
    float* KVp = smf + KVP_OFF;
    float* ksum = smf + KS_OFF;
    float* dn = smf + DN_OFF;

    int tid = threadIdx.x;
    int tx = tid & 15, ty = tid >> 4;
    size_t nbase = (size_t)b * TSEQ + (size_t)c * CHUNK;
    size_t sidx = ((size_t)(b * HEADS + h) * NC + c);

#pragma unroll
    for (int it = 0; it < 16; it++) {
        int lin = tid + it * 256;
        int i = lin >> 6, d = lin & 63;
        size_t g = (nbase + i) * D + h * HD + d;
        Qt[d * SP + i] = g_q[g];
        Kt[d * SP + i] = g_k[g];
    }
#pragma unroll
    for (int it = 0; it < 4; it++) {
        int lin = tid + it * 256;
        int i = lin >> 4, d4 = lin & 15;
        *(float4*)&V[i * SP + d4 * 4] =
            *(const float4*)&g_v[(nbase + i) * D + h * HD + d4 * 4];
    }
#pragma unroll
    for (int it = 0; it < 4; it++) {
        int lin = tid + it * 256;
        int dd = lin >> 4, m4 = lin & 15;
        *(float4*)&KVp[dd * SP + m4 * 4] =
            *(const float4*)&g_ckv[sidx * HD * HD + lin * 4];
    }
    if (tid < HD) ksum[tid] = g_cks[sidx * HD + tid];
    __syncthreads();

    // ---- stage 1: S = mask(Q K^T) ----
    {
        int i0 = ty * 4, j0 = tx * 4;
        float s[4][4];
#pragma unroll
        for (int i = 0; i < 4; i++)
#pragma unroll
            for (int j = 0; j < 4; j++) s[i][j] = 0.f;

#pragma unroll 8
        for (int d = 0; d < HD; d++) {
            float4 q0 = *(const float4*)&Qt[d * SP + i0];
            float4 k0 = *(const float4*)&Kt[d * SP + j0];
            float qa[4] = {q0.x, q0.y, q0.z, q0.w};
            float kb[4] = {k0.x, k0.y, k0.z, k0.w};
#pragma unroll
            for (int i = 0; i < 4; i++)
#pragma unroll
                for (int j = 0; j < 4; j++) s[i][j] += qa[i] * kb[j];
        }
#pragma unroll
        for (int ii = 0; ii < 4; ii++) {
            int i = i0 + ii;
            float4 o0;
            o0.x = (j0 + 0 <= i) ? s[ii][0] : 0.f;
            o0.y = (j0 + 1 <= i) ? s[ii][1] : 0.f;
            o0.z = (j0 + 2 <= i) ? s[ii][2] : 0.f;
            o0.w = (j0 + 3 <= i) ? s[ii][3] : 0.f;
            *(float4*)&S[i * SP + j0] = o0;
        }
    }
    __syncthreads();

    // ---- stage 2: O = S V + Q KVp ; denom ; split-store ----
    {
        int i0 = ty * 4, m0 = tx * 4;
        float acc[4][4];
        float rs[4];
#pragma unroll
        for (int i = 0; i < 4; i++) {
            rs[i] = 0.f;
#pragma unroll
            for (int j = 0; j < 4; j++) acc[i][j] = 0.f;
        }

#pragma unroll 4
        for (int j = 0; j < CHUNK; j++) {
            float4 vv = *(const float4*)&V[j * SP + m0];
            float va[4] = {vv.x, vv.y, vv.z, vv.w};
#pragma unroll
            for (int ii = 0; ii < 4; ii++) {
                float sv = S[(i0 + ii) * SP + j];
                rs[ii] += sv;
#pragma unroll
                for (int mm = 0; mm < 4; mm++) acc[ii][mm] += sv * va[mm];
            }
        }
#pragma unroll 4
        for (int d = 0; d < HD; d++) {
            float4 q0 = *(const float4*)&Qt[d * SP + i0];
            float qa[4] = {q0.x, q0.y, q0.z, q0.w};
            float4 kv = *(const float4*)&KVp[d * SP + m0];
            float ka[4] = {kv.x, kv.y, kv.z, kv.w};
            float kss = ksum[d];
#pragma unroll
            for (int ii = 0; ii < 4; ii++) {
                rs[ii] += qa[ii] * kss;
#pragma unroll
                for (int mm = 0; mm < 4; mm++) acc[ii][mm] += qa[ii] * ka[mm];
            }
        }
        if (tx == 0) {
#pragma unroll
            for (int ii = 0; ii < 4; ii++) dn[i0 + ii] = rs[ii];
        }
        __syncthreads();
#pragma unroll
        for (int ii = 0; ii < 4; ii++) {
            float inv = 1.f / fmaxf(dn[i0 + ii], 1e-6f);
            size_t g = (nbase + i0 + ii) * D + h * HD + m0;
            uint16_t hh[4], ll[4];
#pragma unroll
            for (int mm = 0; mm < 4; mm++)
                split2(acc[ii][mm] * inv, hh[mm], ll[mm]);
            *(uint2*)&g_phi[g] = make_uint2((uint32_t)hh[0] | ((uint32_t)hh[1] << 16),
                                            (uint32_t)hh[2] | ((uint32_t)hh[3] << 16));
            *(uint2*)&g_plo[g] = make_uint2((uint32_t)ll[0] | ((uint32_t)ll[1] << 16),
                                            (uint32_t)ll[2] | ((uint32_t)ll[3] << 16));
        }
    }
}

// ---------------- launch ----------------
extern "C" void kernel_launch(void* const* d_in, const int* in_sizes, int n_in,
                              void* d_out, int out_size)
{
    const float* x  = (const float*)d_in[0];
    const float* Wq = (const float*)d_in[1];
    const float* bq = (const float*)d_in[2];
    const float* Wk = (const float*)d_in[3];
    const float* bk = (const float*)d_in[4];
    const float* Wv = (const float*)d_in[5];
    const float* bv = (const float*)d_in[6];
    const float* Wo = (const float*)d_in[7];
    const float* bo = (const float*)d_in[8];

    int N = in_sizes[0] / D;     // b * t
    int B = N / TSEQ;
    int rowTiles = N / 128;
    int n4x = N * D / 4;

    cudaFuncSetAttribute(mma_gemm,
                         cudaFuncAttributeMaxDynamicSharedMemorySize, GEMM_SMEM);
    cudaFuncSetAttribute(attn_chunk_kernel,
                         cudaFuncAttributeMaxDynamicSharedMemorySize,
                         SM2C_FLOATS * (int)sizeof(float));

    // merged split conversion: weights + x
    convert_all<<<(W4 + n4x + 255) / 256, 256>>>(x, Wq, Wk, Wv, Wo, n4x);

    // fused QKV projection (z = 0,1,2 -> q,k,v); elu+1 on q,k
    dim3 gq(D / 128, rowTiles, 3);
    mma_gemm<<<gq, 256, GEMM_SMEM>>>(0, 0, 0, bq, bk, bv, nullptr, 0x3);

    chunk_sum_kernel<<<dim3(B * NC, HEADS * 2), 256, CS_SMEM>>>();
    prefix_kernel<<<B * HEADS, 256>>>();
    attn_chunk_kernel<<<dim3(B * NC, HEADS), 256,
                        SM2C_FLOATS * sizeof(float)>>>();

    // output projection from split attention output -> d_out
    dim3 go(D / 128, rowTiles, 1);
    mma_gemm<<<go, 256, GEMM_SMEM>>>(1, 3, 3, bo, bo, bo, (float*)d_out, 0x0);
}

// round 11
// speedup vs baseline: 1.1219x; 1.1219x over previous
#include <cuda_runtime.h>
#include <cuda_bf16.h>
#include <cstdint>

#define D 512
#define HEADS 8
#define HD 64
#define TSEQ 1024
#define CHUNK 64
#define NC (TSEQ / CHUNK)   // 16
#define MAXB 4

// ---------------- scratch (no allocations allowed) ----------------
__device__ float g_q[MAXB * TSEQ * D];
__device__ float g_k[MAXB * TSEQ * D];
__device__ float g_v[MAXB * TSEQ * D];
__device__ float g_ckv[MAXB * HEADS * NC * HD * HD];
__device__ float g_cks[MAXB * HEADS * NC * HD];
// bf16 split operands
__device__ __nv_bfloat16 g_whi[4 * D * D];
__device__ __nv_bfloat16 g_wlo[4 * D * D];
__device__ __nv_bfloat16 g_xhi[MAXB * TSEQ * D];
__device__ __nv_bfloat16 g_xlo[MAXB * TSEQ * D];
__device__ __nv_bfloat16 g_phi[MAXB * TSEQ * D];   // post-attention activations
__device__ __nv_bfloat16 g_plo[MAXB * TSEQ * D];

// ---------------- helpers ----------------
__device__ __forceinline__ void split2(float f, uint16_t& h, uint16_t& l) {
    __nv_bfloat16 hb = __float2bfloat16_rn(f);
    float hf = __bfloat162float(hb);
    __nv_bfloat16 lb = __float2bfloat16_rn(f - hf);
    h = __bfloat16_as_ushort(hb);
    l = __bfloat16_as_ushort(lb);
}

__device__ __forceinline__ void mma_bf16(float* d, const uint32_t* a, const uint32_t* b) {
    asm volatile(
        "mma.sync.aligned.m16n8k16.row.col.f32.bf16.bf16.f32 "
        "{%0,%1,%2,%3}, {%4,%5,%6,%7}, {%8,%9}, {%0,%1,%2,%3};"
        : "+f"(d[0]), "+f"(d[1]), "+f"(d[2]), "+f"(d[3])
        : "r"(a[0]), "r"(a[1]), "r"(a[2]), "r"(a[3]), "r"(b[0]), "r"(b[1]));
}

__device__ __forceinline__ uint32_t smem_u32(const void* p) {
    uint32_t a;
    asm("{ .reg .u64 t; cvta.to.shared.u64 t, %1; cvt.u32.u64 %0, t; }"
        : "=r"(a) : "l"(p));
    return a;
}
__device__ __forceinline__ void cp16(uint32_t dst, const void* src) {
    asm volatile("cp.async.cg.shared.global [%0], [%1], 16;"
                 :: "r"(dst), "l"(src));
}
#define CP_COMMIT() asm volatile("cp.async.commit_group;" ::: "memory")
#define CP_WAIT(n)  asm volatile("cp.async.wait_group %0;" :: "n"(n) : "memory")

#define LDSM4(r, addr) \
    asm volatile("ldmatrix.sync.aligned.m8n8.x4.shared.b16 {%0,%1,%2,%3}, [%4];" \
        : "=r"((r)[0]), "=r"((r)[1]), "=r"((r)[2]), "=r"((r)[3]) : "r"(addr))

// ---------------- merged conversion kernel (weights + x) ----------------
#define W4 (4 * D * D / 4)      // 262144 float4s of weights
__global__ void __launch_bounds__(256) convert_all(
    const float* __restrict__ x,
    const float* __restrict__ Wq, const float* __restrict__ Wk,
    const float* __restrict__ Wv, const float* __restrict__ Wo, int n4x)
{
    int gid = blockIdx.x * 256 + threadIdx.x;
    if (gid < W4) {
        int w = gid >> 16;
        int off = gid & 65535;
        const float* src = (w == 0) ? Wq : (w == 1) ? Wk : (w == 2) ? Wv : Wo;
        float4 v = ((const float4*)src)[off];
        float f[4] = {v.x, v.y, v.z, v.w};
        uint16_t h[4], l[4];
#pragma unroll
        for (int j = 0; j < 4; ++j) split2(f[j], h[j], l[j]);
        ((uint2*)(g_whi + (size_t)w * D * D))[off] =
            make_uint2((uint32_t)h[0] | ((uint32_t)h[1] << 16),
                       (uint32_t)h[2] | ((uint32_t)h[3] << 16));
        ((uint2*)(g_wlo + (size_t)w * D * D))[off] =
            make_uint2((uint32_t)l[0] | ((uint32_t)l[1] << 16),
                       (uint32_t)l[2] | ((uint32_t)l[3] << 16));
    } else {
        int i = gid - W4;
        if (i < n4x) {
            float4 v = ((const float4*)x)[i];
            float f[4] = {v.x, v.y, v.z, v.w};
            uint16_t h[4], l[4];
#pragma unroll
            for (int j = 0; j < 4; ++j) split2(f[j], h[j], l[j]);
            ((uint2*)g_xhi)[i] = make_uint2((uint32_t)h[0] | ((uint32_t)h[1] << 16),
                                            (uint32_t)h[2] | ((uint32_t)h[3] << 16));
            ((uint2*)g_xlo)[i] = make_uint2((uint32_t)l[0] | ((uint32_t)l[1] << 16),
                                            (uint32_t)l[2] | ((uint32_t)l[3] << 16));
        }
    }
}

// ---------------- mma.sync split-bf16 GEMM (R9 version: KC=64, ldmatrix) ----------------
#define ROWU 36
#define ARRU (128 * ROWU)      // 4608
#define BUFU (4 * ARRU)        // 18432
#define GEMM_SMEM (2 * BUFU * 4)   // 147456 bytes

// async copy one K-chunk (A/B hi/lo) into smem buffer at byte base sbB
__device__ __forceinline__ void load_chunk_async(
    uint32_t sbB, const uint32_t* Ahi, const uint32_t* Alo,
    const uint32_t* Bhi, const uint32_t* Blo,
    int rowBase, int colBase, int k0u, int tid)
{
#pragma unroll
    for (int it = 0; it < 4; ++it) {
        int lin = tid + it * 256;          // 0..1023
        int r = lin >> 3, q = lin & 7;
        uint32_t dOff = (uint32_t)(r * ROWU + q * 4) * 4;
        cp16(sbB + dOff, Ahi + (size_t)(rowBase + r) * 256 + k0u + q * 4);
        cp16(sbB + ARRU * 4 + dOff, Alo + (size_t)(rowBase + r) * 256 + k0u + q * 4);
        cp16(sbB + 2 * ARRU * 4 + dOff, Bhi + (size_t)(colBase + r) * 256 + k0u + q * 4);
        cp16(sbB + 3 * ARRU * 4 + dOff, Blo + (size_t)(colBase + r) * 256 + k0u + q * 4);
    }
}

__global__ void __launch_bounds__(256, 1) mma_gemm(
    int asel, int wBase, int oselBase,
    const float* __restrict__ bias0, const float* __restrict__ bias1,
    const float* __restrict__ bias2,
    float* __restrict__ Oext, int actmask)
{
    extern __shared__ __align__(16) uint32_t smu[];
    int tid = threadIdx.x, lane = tid & 31, wid = tid >> 5;
    int warpRow = wid >> 2;
    int warpCol = wid & 3;
    int z = blockIdx.z;
    int rowBase = blockIdx.y * 128;
    int colBase = blockIdx.x * 128;

    const uint32_t* Ahi = asel ? (const uint32_t*)g_phi : (const uint32_t*)g_xhi;
    const uint32_t* Alo = asel ? (const uint32_t*)g_plo : (const uint32_t*)g_xlo;
    int wz = wBase + z;
    const uint32_t* Bhi = (const uint32_t*)g_whi + (size_t)wz * (D * D / 2);
    const uint32_t* Blo = (const uint32_t*)g_wlo + (size_t)wz * (D * D / 2);
    const float* bias = (z == 0) ? bias0 : (z == 1) ? bias1 : bias2;
    int osel = oselBase + z;
    float* O = (osel == 3) ? Oext : (osel == 0 ? g_q : (osel == 1 ? g_k : g_v));
    int act = (actmask >> z) & 1;

    uint32_t sbB = smem_u32(smu);

    // ldmatrix lane addressing
    int lrA = lane & 15, lhA = lane >> 4;
    int brB = ((lane >> 4) << 3) + (lane & 7);
    int bhB = (lane >> 3) & 1;

    float acc[4][4][4];
#pragma unroll
    for (int mt = 0; mt < 4; ++mt)
#pragma unroll
        for (int nt = 0; nt < 4; ++nt)
#pragma unroll
            for (int r = 0; r < 4; ++r) acc[mt][nt][r] = 0.f;

    load_chunk_async(sbB, Ahi, Alo, Bhi, Blo, rowBase, colBase, 0, tid);
    CP_COMMIT();

    for (int c = 0; c < 8; ++c) {
        int buf = c & 1;
        if (c < 7) {
            load_chunk_async(sbB + ((c + 1) & 1) * BUFU * 4,
                             Ahi, Alo, Bhi, Blo, rowBase, colBase,
                             (c + 1) * 32, tid);
            CP_COMMIT();
            CP_WAIT(1);
        } else {
            CP_WAIT(0);
        }
        __syncthreads();

        uint32_t aBH = sbB + (uint32_t)buf * BUFU * 4;
        uint32_t aBL = aBH + ARRU * 4;
        uint32_t bBH = aBH + 2 * ARRU * 4;
        uint32_t bBL = aBH + 3 * ARRU * 4;
#pragma unroll
        for (int ks = 0; ks < 4; ++ks) {
            uint32_t ahi[4][4], alo[4][4], bhi[4][2], blo[4][2];
#pragma unroll
            for (int mt = 0; mt < 4; ++mt) {
                uint32_t off = (uint32_t)((warpRow * 64 + mt * 16 + lrA) * ROWU
                                          + ks * 8 + lhA * 4) * 4;
                LDSM4(ahi[mt], aBH + off);
                LDSM4(alo[mt], aBL + off);
            }
#pragma unroll
            for (int p = 0; p < 2; ++p) {
                uint32_t off = (uint32_t)((warpCol * 32 + p * 16 + brB) * ROWU
                                          + ks * 8 + bhB * 4) * 4;
                uint32_t t0[4], t1[4];
                LDSM4(t0, bBH + off);
                LDSM4(t1, bBL + off);
                bhi[2 * p][0] = t0[0]; bhi[2 * p][1] = t0[1];
                bhi[2 * p + 1][0] = t0[2]; bhi[2 * p + 1][1] = t0[3];
                blo[2 * p][0] = t1[0]; blo[2 * p][1] = t1[1];
                blo[2 * p + 1][0] = t1[2]; blo[2 * p + 1][1] = t1[3];
            }
#pragma unroll
            for (int mt = 0; mt < 4; ++mt)
#pragma unroll
                for (int nt = 0; nt < 4; ++nt) {
                    mma_bf16(acc[mt][nt], ahi[mt], bhi[nt]);
                    mma_bf16(acc[mt][nt], ahi[mt], blo[nt]);
                    mma_bf16(acc[mt][nt], alo[mt], bhi[nt]);
                }
        }
        __syncthreads();
    }

#pragma unroll
    for (int mt = 0; mt < 4; ++mt) {
        int r0 = rowBase + warpRow * 64 + mt * 16 + (lane >> 2);
#pragma unroll
        for (int nt = 0; nt < 4; ++nt) {
            int cc = colBase + warpCol * 32 + nt * 8 + (lane & 3) * 2;
            float b0 = bias[cc], b1 = bias[cc + 1];
            float v0 = acc[mt][nt][0] + b0;
            float v1 = acc[mt][nt][1] + b1;
            float v2 = acc[mt][nt][2] + b0;
            float v3 = acc[mt][nt][3] + b1;
            if (act) {
                v0 = (v0 > 0.f) ? v0 + 1.f : __expf(v0);
                v1 = (v1 > 0.f) ? v1 + 1.f : __expf(v1);
                v2 = (v2 > 0.f) ? v2 + 1.f : __expf(v2);
                v3 = (v3 > 0.f) ? v3 + 1.f : __expf(v3);
            }
            *(float2*)&O[(size_t)r0 * D + cc] = make_float2(v0, v1);
            *(float2*)&O[(size_t)(r0 + 8) * D + cc] = make_float2(v2, v3);
        }
    }
}

// ---------------- per-chunk local sums (CHUNK=64, m-split x2) ----------------
__global__ void __launch_bounds__(256) chunk_sum_kernel()
{
    int bc = blockIdx.x;            // b*NC + c
    int hm = blockIdx.y;
    int h = hm >> 1, mh = hm & 1;
    int b = bc / NC, c = bc % NC;
    extern __shared__ __align__(16) float smf[];
    float* ks = smf;                   // [CHUNK][HD]
    float* vs = smf + CHUNK * HD;      // [CHUNK][32]

    int tid = threadIdx.x;
    size_t nbase = (size_t)b * TSEQ + (size_t)c * CHUNK;

#pragma unroll
    for (int it = 0; it < 4; it++) {
        int lin = tid + it * 256;
        int t = lin >> 4;
        int d4 = lin & 15;
        ((float4*)ks)[lin] = *(const float4*)&g_k[(nbase + t) * D + h * HD + d4 * 4];
    }
#pragma unroll
    for (int it = 0; it < 2; it++) {
        int lin = tid + it * 256;
        int t = lin >> 3;
        int m4 = lin & 7;
        ((float4*)vs)[lin] =
            *(const float4*)&g_v[(nbase + t) * D + h * HD + mh * 32 + m4 * 4];
    }
    __syncthreads();

    int d0 = (tid >> 4) * 4;
    int m0 = (tid & 15) * 2;
    float acc[4][2];
#pragma unroll
    for (int i = 0; i < 4; i++) { acc[i][0] = 0.f; acc[i][1] = 0.f; }

#pragma unroll 8
    for (int t = 0; t < CHUNK; t++) {
        float4 kd = *(const float4*)&ks[t * HD + d0];
        float2 vm = *(const float2*)&vs[t * 32 + m0];
        float ka[4] = {kd.x, kd.y, kd.z, kd.w};
#pragma unroll
        for (int i = 0; i < 4; i++) {
            acc[i][0] += ka[i] * vm.x;
            acc[i][1] += ka[i] * vm.y;
        }
    }

    size_t sidx = ((size_t)(b * HEADS + h) * NC + c);
    float* ckv = g_ckv + sidx * HD * HD;
#pragma unroll
    for (int i = 0; i < 4; i++)
        *(float2*)&ckv[(d0 + i) * HD + mh * 32 + m0] = make_float2(acc[i][0], acc[i][1]);

    if (mh == 0 && tid < HD) {
        float s = 0.f;
#pragma unroll 8
        for (int t = 0; t < CHUNK; t++) s += ks[t * HD + tid];
        g_cks[sidx * HD + tid] = s;
    }
}
#define CS_SMEM ((CHUNK * HD + CHUNK * 32) * 4)   // 24576 B

// ---------------- exclusive prefix over chunks per (b,h) ----------------
// One element-chain per thread: all NC loads issued up front (MLP=NC),
// prefix in registers, then NC stores. grid (B*HEADS, 16) x 256 threads.
__global__ void __launch_bounds__(256) prefix_kernel()
{
    int bh = blockIdx.x;
    int e = blockIdx.y * 256 + threadIdx.x;    // 0..4095
    float* base = g_ckv + (size_t)bh * NC * HD * HD + e;

    float v[NC];
#pragma unroll
    for (int c = 0; c < NC; c++) v[c] = base[c * HD * HD];   // independent loads
    float carry = 0.f;
#pragma unroll
    for (int c = 0; c < NC; c++) {
        float t = v[c];
        base[c * HD * HD] = carry;
        carry += t;
    }

    if (blockIdx.y == 0 && threadIdx.x < HD) {
        float* kb = g_cks + (size_t)bh * NC * HD + threadIdx.x;
        float w[NC];
#pragma unroll
        for (int c = 0; c < NC; c++) w[c] = kb[c * HD];
        float kc = 0.f;
#pragma unroll
        for (int c = 0; c < NC; c++) {
            float t = w[c];
            kb[c * HD] = kc;
            kc += t;
        }
    }
}

// ---------------- per-chunk attention (CHUNK=64) ----------------
#define SP 68
#define QT_OFF 0
#define KT_OFF (HD * SP)                 // 4352
#define V_OFF  (KT_OFF + HD * SP)        // 8704
#define S_OFF  (V_OFF + CHUNK * SP)      // 13056
#define KVP_OFF (S_OFF + CHUNK * SP)     // 17408
#define KS_OFF (KVP_OFF + HD * SP)       // 21760
#define DN_OFF (KS_OFF + HD)             // 21824
#define SM2C_FLOATS (DN_OFF + CHUNK)     // 21888 floats = 87552 B

__global__ void __launch_bounds__(256) attn_chunk_kernel()
{
    int bc = blockIdx.x;
    int h = blockIdx.y;
    int b = bc / NC, c = bc % NC;
    extern __shared__ __align__(16) float smf[];
    float* Qt = smf + QT_OFF;
    float* Kt = smf + KT_OFF;
    float* V  = smf + V_OFF;
    float* S  = smf + S_OFF;
    float* KVp = smf + KVP_OFF;
    float* ksum = smf + KS_OFF;
    float* dn = smf + DN_OFF;

    int tid = threadIdx.x;
    int tx = tid & 15, ty = tid >> 4;
    size_t nbase = (size_t)b * TSEQ + (size_t)c * CHUNK;
    size_t sidx = ((size_t)(b * HEADS + h) * NC + c);

#pragma unroll
    for (int it = 0; it < 16; it++) {
        int lin = tid + it * 256;
        int i = lin >> 6, d = lin & 63;
        size_t g = (nbase + i) * D + h * HD + d;
        Qt[d * SP + i] = g_q[g];
        Kt[d * SP + i] = g_k[g];
    }
#pragma unroll
    for (int it = 0; it < 4; it++) {
        int lin = tid + it * 256;
        int i = lin >> 4, d4 = lin & 15;
        *(float4*)&V[i * SP + d4 * 4] =
            *(const float4*)&g_v[(nbase + i) * D + h * HD + d4 * 4];
    }
#pragma unroll
    for (int it = 0; it < 4; it++) {
        int lin = tid + it * 256;
        int dd = lin >> 4, m4 = lin & 15;
        *(float4*)&KVp[dd * SP + m4 * 4] =
            *(const float4*)&g_ckv[sidx * HD * HD + lin * 4];
    }
    if (tid < HD) ksum[tid] = g_cks[sidx * HD + tid];
    __syncthreads();

    // ---- stage 1: S = mask(Q K^T) ----
    {
        int i0 = ty * 4, j0 = tx * 4;
        float s[4][4];
#pragma unroll
        for (int i = 0; i < 4; i++)
#pragma unroll
            for (int j = 0; j < 4; j++) s[i][j] = 0.f;

#pragma unroll 8
        for (int d = 0; d < HD; d++) {
            float4 q0 = *(const float4*)&Qt[d * SP + i0];
            float4 k0 = *(const float4*)&Kt[d * SP + j0];
            float qa[4] = {q0.x, q0.y, q0.z, q0.w};
            float kb[4] = {k0.x, k0.y, k0.z, k0.w};
#pragma unroll
            for (int i = 0; i < 4; i++)
#pragma unroll
                for (int j = 0; j < 4; j++) s[i][j] += qa[i] * kb[j];
        }
#pragma unroll
        for (int ii = 0; ii < 4; ii++) {
            int i = i0 + ii;
            float4 o0;
            o0.x = (j0 + 0 <= i) ? s[ii][0] : 0.f;
            o0.y = (j0 + 1 <= i) ? s[ii][1] : 0.f;
            o0.z = (j0 + 2 <= i) ? s[ii][2] : 0.f;
            o0.w = (j0 + 3 <= i) ? s[ii][3] : 0.f;
            *(float4*)&S[i * SP + j0] = o0;
        }
    }
    __syncthreads();

    // ---- stage 2: O = S V + Q KVp ; denom ; split-store ----
    {
        int i0 = ty * 4, m0 = tx * 4;
        float acc[4][4];
        float rs[4];
#pragma unroll
        for (int i = 0; i < 4; i++) {
            rs[i] = 0.f;
#pragma unroll
            for (int j = 0; j < 4; j++) acc[i][j] = 0.f;
        }

#pragma unroll 4
        for (int j = 0; j < CHUNK; j++) {
            float4 vv = *(const float4*)&V[j * SP + m0];
            float va[4] = {vv.x, vv.y, vv.z, vv.w};
#pragma unroll
            for (int ii = 0; ii < 4; ii++) {
                float sv = S[(i0 + ii) * SP + j];
                rs[ii] += sv;
#pragma unroll
                for (int mm = 0; mm < 4; mm++) acc[ii][mm] += sv * va[mm];
            }
        }
#pragma unroll 4
        for (int d = 0; d < HD; d++) {
            float4 q0 = *(const float4*)&Qt[d * SP + i0];
            float qa[4] = {q0.x, q0.y, q0.z, q0.w};
            float4 kv = *(const float4*)&KVp[d * SP + m0];
            float ka[4] = {kv.x, kv.y, kv.z, kv.w};
            float kss = ksum[d];
#pragma unroll
            for (int ii = 0; ii < 4; ii++) {
                rs[ii] += qa[ii] * kss;
#pragma unroll
                for (int mm = 0; mm < 4; mm++) acc[ii][mm] += qa[ii] * ka[mm];
            }
        }
        if (tx == 0) {
#pragma unroll
            for (int ii = 0; ii < 4; ii++) dn[i0 + ii] = rs[ii];
        }
        __syncthreads();
#pragma unroll
        for (int ii = 0; ii < 4; ii++) {
            float inv = 1.f / fmaxf(dn[i0 + ii], 1e-6f);
            size_t g = (nbase + i0 + ii) * D + h * HD + m0;
            uint16_t hh[4], ll[4];
#pragma unroll
            for (int mm = 0; mm < 4; mm++)
                split2(acc[ii][mm] * inv, hh[mm], ll[mm]);
            *(uint2*)&g_phi[g] = make_uint2((uint32_t)hh[0] | ((uint32_t)hh[1] << 16),
                                            (uint32_t)hh[2] | ((uint32_t)hh[3] << 16));
            *(uint2*)&g_plo[g] = make_uint2((uint32_t)ll[0] | ((uint32_t)ll[1] << 16),
                                            (uint32_t)ll[2] | ((uint32_t)ll[3] << 16));
        }
    }
}

// ---------------- launch ----------------
extern "C" void kernel_launch(void* const* d_in, const int* in_sizes, int n_in,
                              void* d_out, int out_size)
{
    const float* x  = (const float*)d_in[0];
    const float* Wq = (const float*)d_in[1];
    const float* bq = (const float*)d_in[2];
    const float* Wk = (const float*)d_in[3];
    const float* bk = (const float*)d_in[4];
    const float* Wv = (const float*)d_in[5];
    const float* bv = (const float*)d_in[6];
    const float* Wo = (const float*)d_in[7];
    const float* bo = (const float*)d_in[8];

    int N = in_sizes[0] / D;     // b * t
    int B = N / TSEQ;
    int rowTiles = N / 128;
    int n4x = N * D / 4;

    cudaFuncSetAttribute(mma_gemm,
                         cudaFuncAttributeMaxDynamicSharedMemorySize, GEMM_SMEM);
    cudaFuncSetAttribute(attn_chunk_kernel,
                         cudaFuncAttributeMaxDynamicSharedMemorySize,
                         SM2C_FLOATS * (int)sizeof(float));

    // merged split conversion: weights + x
    convert_all<<<(W4 + n4x + 255) / 256, 256>>>(x, Wq, Wk, Wv, Wo, n4x);

    // fused QKV projection (z = 0,1,2 -> q,k,v); elu+1 on q,k
    dim3 gq(D / 128, rowTiles, 3);
    mma_gemm<<<gq, 256, GEMM_SMEM>>>(0, 0, 0, bq, bk, bv, nullptr, 0x3);

    chunk_sum_kernel<<<dim3(B * NC, HEADS * 2), 256, CS_SMEM>>>();
    prefix_kernel<<<dim3(B * HEADS, 16), 256>>>();
    attn_chunk_kernel<<<dim3(B * NC, HEADS), 256,
                        SM2C_FLOATS * sizeof(float)>>>();

    // output projection from split attention output -> d_out
    dim3 go(D / 128, rowTiles, 1);
    mma_gemm<<<go, 256, GEMM_SMEM>>>(1, 3, 3, bo, bo, bo, (float*)d_out, 0x0);
}

// round 12
// speedup vs baseline: 1.4014x; 1.2491x over previous
#include <cuda_runtime.h>
#include <cuda_bf16.h>
#include <cstdint>

#define D 512
#define HEADS 8
#define HD 64
#define TSEQ 1024
#define CHUNK 64
#define NC (TSEQ / CHUNK)   // 16
#define MAXB 4

// ---------------- scratch (no allocations allowed) ----------------
__device__ float g_q[MAXB * TSEQ * D];
__device__ float g_k[MAXB * TSEQ * D];
__device__ float g_v[MAXB * TSEQ * D];
__device__ float g_ckv[MAXB * HEADS * NC * HD * HD];
__device__ float g_cks[MAXB * HEADS * NC * HD];
// bf16 split operands
__device__ __nv_bfloat16 g_whi[4 * D * D];
__device__ __nv_bfloat16 g_wlo[4 * D * D];
__device__ __nv_bfloat16 g_xhi[MAXB * TSEQ * D];
__device__ __nv_bfloat16 g_xlo[MAXB * TSEQ * D];
__device__ __nv_bfloat16 g_phi[MAXB * TSEQ * D];   // post-attention activations
__device__ __nv_bfloat16 g_plo[MAXB * TSEQ * D];

// ---------------- helpers ----------------
__device__ __forceinline__ void split2(float f, uint16_t& h, uint16_t& l) {
    __nv_bfloat16 hb = __float2bfloat16_rn(f);
    float hf = __bfloat162float(hb);
    __nv_bfloat16 lb = __float2bfloat16_rn(f - hf);
    h = __bfloat16_as_ushort(hb);
    l = __bfloat16_as_ushort(lb);
}

__device__ __forceinline__ void mma_bf16(float* d, const uint32_t* a, const uint32_t* b) {
    asm volatile(
        "mma.sync.aligned.m16n8k16.row.col.f32.bf16.bf16.f32 "
        "{%0,%1,%2,%3}, {%4,%5,%6,%7}, {%8,%9}, {%0,%1,%2,%3};"
        : "+f"(d[0]), "+f"(d[1]), "+f"(d[2]), "+f"(d[3])
        : "r"(a[0]), "r"(a[1]), "r"(a[2]), "r"(a[3]), "r"(b[0]), "r"(b[1]));
}

__device__ __forceinline__ uint32_t smem_u32(const void* p) {
    uint32_t a;
    asm("{ .reg .u64 t; cvta.to.shared.u64 t, %1; cvt.u32.u64 %0, t; }"
        : "=r"(a) : "l"(p));
    return a;
}
__device__ __forceinline__ void cp16(uint32_t dst, const void* src) {
    asm volatile("cp.async.cg.shared.global [%0], [%1], 16;"
                 :: "r"(dst), "l"(src));
}
#define CP_COMMIT() asm volatile("cp.async.commit_group;" ::: "memory")
#define CP_WAIT(n)  asm volatile("cp.async.wait_group %0;" :: "n"(n) : "memory")

#define LDSM4(r, addr) \
    asm volatile("ldmatrix.sync.aligned.m8n8.x4.shared.b16 {%0,%1,%2,%3}, [%4];" \
        : "=r"((r)[0]), "=r"((r)[1]), "=r"((r)[2]), "=r"((r)[3]) : "r"(addr))

// ---------------- merged conversion kernel (weights + x) ----------------
#define W4 (4 * D * D / 4)      // 262144 float4s of weights
__global__ void __launch_bounds__(256) convert_all(
    const float* __restrict__ x,
    const float* __restrict__ Wq, const float* __restrict__ Wk,
    const float* __restrict__ Wv, const float* __restrict__ Wo, int n4x)
{
    int gid = blockIdx.x * 256 + threadIdx.x;
    if (gid < W4) {
        int w = gid >> 16;
        int off = gid & 65535;
        const float* src = (w == 0) ? Wq : (w == 1) ? Wk : (w == 2) ? Wv : Wo;
        float4 v = ((const float4*)src)[off];
        float f[4] = {v.x, v.y, v.z, v.w};
        uint16_t h[4], l[4];
#pragma unroll
        for (int j = 0; j < 4; ++j) split2(f[j], h[j], l[j]);
        ((uint2*)(g_whi + (size_t)w * D * D))[off] =
            make_uint2((uint32_t)h[0] | ((uint32_t)h[1] << 16),
                       (uint32_t)h[2] | ((uint32_t)h[3] << 16));
        ((uint2*)(g_wlo + (size_t)w * D * D))[off] =
            make_uint2((uint32_t)l[0] | ((uint32_t)l[1] << 16),
                       (uint32_t)l[2] | ((uint32_t)l[3] << 16));
    } else {
        int i = gid - W4;
        if (i < n4x) {
            float4 v = ((const float4*)x)[i];
            float f[4] = {v.x, v.y, v.z, v.w};
            uint16_t h[4], l[4];
#pragma unroll
            for (int j = 0; j < 4; ++j) split2(f[j], h[j], l[j]);
            ((uint2*)g_xhi)[i] = make_uint2((uint32_t)h[0] | ((uint32_t)h[1] << 16),
                                            (uint32_t)h[2] | ((uint32_t)h[3] << 16));
            ((uint2*)g_xlo)[i] = make_uint2((uint32_t)l[0] | ((uint32_t)l[1] << 16),
                                            (uint32_t)l[2] | ((uint32_t)l[3] << 16));
        }
    }
}

// ---------------- mma.sync split-bf16 GEMM (tile 128x64, 2 CTAs/SM) ----------------
// smem per buffer: AHI/ALO 128x36 u32, BHI/BLO 64x36 u32 = 13824 u32 = 55296 B.
// Double-buffered: 110592 B -> 2 CTAs/SM. Row stride 144B odd-16B -> ldmatrix OK.
#define ROWU 36
#define ARRUA (128 * ROWU)     // 4608
#define ARRUB (64 * ROWU)      // 2304
#define BUFU (2 * ARRUA + 2 * ARRUB)   // 13824
#define GEMM_SMEM (2 * BUFU * 4)       // 110592 bytes

// async copy one K-chunk (A 128 rows, B 64 rows; hi/lo) into buffer at byte base sbB
__device__ __forceinline__ void load_chunk_async(
    uint32_t sbB, const uint32_t* Ahi, const uint32_t* Alo,
    const uint32_t* Bhi, const uint32_t* Blo,
    int rowBase, int colBase, int k0u, int tid)
{
#pragma unroll
    for (int it = 0; it < 4; ++it) {
        int lin = tid + it * 256;          // 0..1023
        int r = lin >> 3, q = lin & 7;
        uint32_t dOff = (uint32_t)(r * ROWU + q * 4) * 4;
        cp16(sbB + dOff, Ahi + (size_t)(rowBase + r) * 256 + k0u + q * 4);
        cp16(sbB + ARRUA * 4 + dOff, Alo + (size_t)(rowBase + r) * 256 + k0u + q * 4);
    }
#pragma unroll
    for (int it = 0; it < 2; ++it) {
        int lin = tid + it * 256;          // 0..511
        int r = lin >> 3, q = lin & 7;
        uint32_t dOff = (uint32_t)(r * ROWU + q * 4) * 4;
        cp16(sbB + 2 * ARRUA * 4 + dOff, Bhi + (size_t)(colBase + r) * 256 + k0u + q * 4);
        cp16(sbB + (2 * ARRUA + ARRUB) * 4 + dOff,
             Blo + (size_t)(colBase + r) * 256 + k0u + q * 4);
    }
}

__global__ void __launch_bounds__(256, 2) mma_gemm(
    int asel, int wBase, int oselBase,
    const float* __restrict__ bias0, const float* __restrict__ bias1,
    const float* __restrict__ bias2,
    float* __restrict__ Oext, int actmask)
{
    extern __shared__ __align__(16) uint32_t smu[];
    int tid = threadIdx.x, lane = tid & 31, wid = tid >> 5;
    int warpRow = wid >> 2;    // 0..1 (64 rows each)
    int warpCol = wid & 3;     // 0..3 (16 cols each)
    int z = blockIdx.z;
    int rowBase = blockIdx.y * 128;
    int colBase = blockIdx.x * 64;

    const uint32_t* Ahi = asel ? (const uint32_t*)g_phi : (const uint32_t*)g_xhi;
    const uint32_t* Alo = asel ? (const uint32_t*)g_plo : (const uint32_t*)g_xlo;
    int wz = wBase + z;
    const uint32_t* Bhi = (const uint32_t*)g_whi + (size_t)wz * (D * D / 2);
    const uint32_t* Blo = (const uint32_t*)g_wlo + (size_t)wz * (D * D / 2);
    const float* bias = (z == 0) ? bias0 : (z == 1) ? bias1 : bias2;
    int osel = oselBase + z;
    float* O = (osel == 3) ? Oext : (osel == 0 ? g_q : (osel == 1 ? g_k : g_v));
    int act = (actmask >> z) & 1;

    uint32_t sbB = smem_u32(smu);

    // ldmatrix lane addressing
    int lrA = lane & 15, lhA = lane >> 4;
    int brB = ((lane >> 4) << 3) + (lane & 7);
    int bhB = (lane >> 3) & 1;

    float acc[4][2][4];
#pragma unroll
    for (int mt = 0; mt < 4; ++mt)
#pragma unroll
        for (int nt = 0; nt < 2; ++nt)
#pragma unroll
            for (int r = 0; r < 4; ++r) acc[mt][nt][r] = 0.f;

    load_chunk_async(sbB, Ahi, Alo, Bhi, Blo, rowBase, colBase, 0, tid);
    CP_COMMIT();

    for (int c = 0; c < 8; ++c) {
        int buf = c & 1;
        if (c < 7) {
            load_chunk_async(sbB + ((c + 1) & 1) * BUFU * 4,
                             Ahi, Alo, Bhi, Blo, rowBase, colBase,
                             (c + 1) * 32, tid);
            CP_COMMIT();
            CP_WAIT(1);
        } else {
            CP_WAIT(0);
        }
        __syncthreads();

        uint32_t aBH = sbB + (uint32_t)buf * BUFU * 4;
        uint32_t aBL = aBH + ARRUA * 4;
        uint32_t bBH = aBH + 2 * ARRUA * 4;
        uint32_t bBL = aBH + (2 * ARRUA + ARRUB) * 4;
#pragma unroll
        for (int ks = 0; ks < 4; ++ks) {
            uint32_t ahi[4][4], alo[4][4];
#pragma unroll
            for (int mt = 0; mt < 4; ++mt) {
                uint32_t off = (uint32_t)((warpRow * 64 + mt * 16 + lrA) * ROWU
                                          + ks * 8 + lhA * 4) * 4;
                LDSM4(ahi[mt], aBH + off);
                LDSM4(alo[mt], aBL + off);
            }
            uint32_t off = (uint32_t)((warpCol * 16 + brB) * ROWU
                                      + ks * 8 + bhB * 4) * 4;
            uint32_t t0[4], t1[4];
            LDSM4(t0, bBH + off);
            LDSM4(t1, bBL + off);
#pragma unroll
            for (int mt = 0; mt < 4; ++mt)
#pragma unroll
                for (int q = 0; q < 2; ++q) {
                    mma_bf16(acc[mt][q], ahi[mt], &t0[2 * q]);
                    mma_bf16(acc[mt][q], ahi[mt], &t1[2 * q]);
                    mma_bf16(acc[mt][q], alo[mt], &t0[2 * q]);
                }
        }
        __syncthreads();
    }

#pragma unroll
    for (int mt = 0; mt < 4; ++mt) {
        int r0 = rowBase + warpRow * 64 + mt * 16 + (lane >> 2);
#pragma unroll
        for (int nt = 0; nt < 2; ++nt) {
            int cc = colBase + warpCol * 16 + nt * 8 + (lane & 3) * 2;
            float b0 = bias[cc], b1 = bias[cc + 1];
            float v0 = acc[mt][nt][0] + b0;
            float v1 = acc[mt][nt][1] + b1;
            float v2 = acc[mt][nt][2] + b0;
            float v3 = acc[mt][nt][3] + b1;
            if (act) {
                v0 = (v0 > 0.f) ? v0 + 1.f : __expf(v0);
                v1 = (v1 > 0.f) ? v1 + 1.f : __expf(v1);
                v2 = (v2 > 0.f) ? v2 + 1.f : __expf(v2);
                v3 = (v3 > 0.f) ? v3 + 1.f : __expf(v3);
            }
            *(float2*)&O[(size_t)r0 * D + cc] = make_float2(v0, v1);
            *(float2*)&O[(size_t)(r0 + 8) * D + cc] = make_float2(v2, v3);
        }
    }
}

// ---------------- per-chunk local sums (CHUNK=64, m-split x2) ----------------
__global__ void __launch_bounds__(256) chunk_sum_kernel()
{
    int bc = blockIdx.x;            // b*NC + c
    int hm = blockIdx.y;
    int h = hm >> 1, mh = hm & 1;
    int b = bc / NC, c = bc % NC;
    extern __shared__ __align__(16) float smf[];
    float* ks = smf;                   // [CHUNK][HD]
    float* vs = smf + CHUNK * HD;      // [CHUNK][32]

    int tid = threadIdx.x;
    size_t nbase = (size_t)b * TSEQ + (size_t)c * CHUNK;

#pragma unroll
    for (int it = 0; it < 4; it++) {
        int lin = tid + it * 256;
        int t = lin >> 4;
        int d4 = lin & 15;
        ((float4*)ks)[lin] = *(const float4*)&g_k[(nbase + t) * D + h * HD + d4 * 4];
    }
#pragma unroll
    for (int it = 0; it < 2; it++) {
        int lin = tid + it * 256;
        int t = lin >> 3;
        int m4 = lin & 7;
        ((float4*)vs)[lin] =
            *(const float4*)&g_v[(nbase + t) * D + h * HD + mh * 32 + m4 * 4];
    }
    __syncthreads();

    int d0 = (tid >> 4) * 4;
    int m0 = (tid & 15) * 2;
    float acc[4][2];
#pragma unroll
    for (int i = 0; i < 4; i++) { acc[i][0] = 0.f; acc[i][1] = 0.f; }

#pragma unroll 8
    for (int t = 0; t < CHUNK; t++) {
        float4 kd = *(const float4*)&ks[t * HD + d0];
        float2 vm = *(const float2*)&vs[t * 32 + m0];
        float ka[4] = {kd.x, kd.y, kd.z, kd.w};
#pragma unroll
        for (int i = 0; i < 4; i++) {
            acc[i][0] += ka[i] * vm.x;
            acc[i][1] += ka[i] * vm.y;
        }
    }

    size_t sidx = ((size_t)(b * HEADS + h) * NC + c);
    float* ckv = g_ckv + sidx * HD * HD;
#pragma unroll
    for (int i = 0; i < 4; i++)
        *(float2*)&ckv[(d0 + i) * HD + mh * 32 + m0] = make_float2(acc[i][0], acc[i][1]);

    if (mh == 0 && tid < HD) {
        float s = 0.f;
#pragma unroll 8
        for (int t = 0; t < CHUNK; t++) s += ks[t * HD + tid];
        g_cks[sidx * HD + tid] = s;
    }
}
#define CS_SMEM ((CHUNK * HD + CHUNK * 32) * 4)   // 24576 B

// ---------------- exclusive prefix over chunks per (b,h) ----------------
__global__ void __launch_bounds__(256) prefix_kernel()
{
    int bh = blockIdx.x;
    int e = blockIdx.y * 256 + threadIdx.x;    // 0..4095
    float* base = g_ckv + (size_t)bh * NC * HD * HD + e;

    float v[NC];
#pragma unroll
    for (int c = 0; c < NC; c++) v[c] = base[c * HD * HD];
    float carry = 0.f;
#pragma unroll
    for (int c = 0; c < NC; c++) {
        float t = v[c];
        base[c * HD * HD] = carry;
        carry += t;
    }

    if (blockIdx.y == 0 && threadIdx.x < HD) {
        float* kb = g_cks + (size_t)bh * NC * HD + threadIdx.x;
        float w[NC];
#pragma unroll
        for (int c = 0; c < NC; c++) w[c] = kb[c * HD];
        float kc = 0.f;
#pragma unroll
        for (int c = 0; c < NC; c++) {
            float t = w[c];
            kb[c * HD] = kc;
            kc += t;
        }
    }
}

// ---------------- per-chunk attention (CHUNK=64) ----------------
#define SP 68
#define QT_OFF 0
#define KT_OFF (HD * SP)                 // 4352
#define V_OFF  (KT_OFF + HD * SP)        // 8704
#define S_OFF  (V_OFF + CHUNK * SP)      // 13056
#define KVP_OFF (S_OFF + CHUNK * SP)     // 17408
#define KS_OFF (KVP_OFF + HD * SP)       // 21760
#define DN_OFF (KS_OFF + HD)             // 21824
#define SM2C_FLOATS (DN_OFF + CHUNK)     // 21888 floats = 87552 B

__global__ void __launch_bounds__(256) attn_chunk_kernel()
{
    int bc = blockIdx.x;
    int h = blockIdx.y;
    int b = bc / NC, c = bc % NC;
    extern __shared__ __align__(16) float smf[];
    float* Qt = smf + QT_OFF;
    float* Kt = smf + KT_OFF;
    float* V  = smf + V_OFF;
    float* S  = smf + S_OFF;
    float* KVp = smf + KVP_OFF;
    float* ksum = smf + KS_OFF;
    float* dn = smf + DN_OFF;

    int tid = threadIdx.x;
    int tx = tid & 15, ty = tid >> 4;
    size_t nbase = (size_t)b * TSEQ + (size_t)c * CHUNK;
    size_t sidx = ((size_t)(b * HEADS + h) * NC + c);

#pragma unroll
    for (int it = 0; it < 16; it++) {
        int lin = tid + it * 256;
        int i = lin >> 6, d = lin & 63;
        size_t g = (nbase + i) * D + h * HD + d;
        Qt[d * SP + i] = g_q[g];
        Kt[d * SP + i] = g_k[g];
    }
#pragma unroll
    for (int it = 0; it < 4; it++) {
        int lin = tid + it * 256;
        int i = lin >> 4, d4 = lin & 15;
        *(float4*)&V[i * SP + d4 * 4] =
            *(const float4*)&g_v[(nbase + i) * D + h * HD + d4 * 4];
    }
#pragma unroll
    for (int it = 0; it < 4; it++) {
        int lin = tid + it * 256;
        int dd = lin >> 4, m4 = lin & 15;
        *(float4*)&KVp[dd * SP + m4 * 4] =
            *(const float4*)&g_ckv[sidx * HD * HD + lin * 4];
    }
    if (tid < HD) ksum[tid] = g_cks[sidx * HD + tid];
    __syncthreads();

    // ---- stage 1: S = mask(Q K^T) ----
    {
        int i0 = ty * 4, j0 = tx * 4;
        float s[4][4];
#pragma unroll
        for (int i = 0; i < 4; i++)
#pragma unroll
            for (int j = 0; j < 4; j++) s[i][j] = 0.f;

#pragma unroll 8
        for (int d = 0; d < HD; d++) {
            float4 q0 = *(const float4*)&Qt[d * SP + i0];
            float4 k0 = *(const float4*)&Kt[d * SP + j0];
            float qa[4] = {q0.x, q0.y, q0.z, q0.w};
            float kb[4] = {k0.x, k0.y, k0.z, k0.w};
#pragma unroll
            for (int i = 0; i < 4; i++)
#pragma unroll
                for (int j = 0; j < 4; j++) s[i][j] += qa[i] * kb[j];
        }
#pragma unroll
        for (int ii = 0; ii < 4; ii++) {
            int i = i0 + ii;
            float4 o0;
            o0.x = (j0 + 0 <= i) ? s[ii][0] : 0.f;
            o0.y = (j0 + 1 <= i) ? s[ii][1] : 0.f;
            o0.z = (j0 + 2 <= i) ? s[ii][2] : 0.f;
            o0.w = (j0 + 3 <= i) ? s[ii][3] : 0.f;
            *(float4*)&S[i * SP + j0] = o0;
        }
    }
    __syncthreads();

    // ---- stage 2: O = S V + Q KVp ; denom ; split-store ----
    {
        int i0 = ty * 4, m0 = tx * 4;
        float acc[4][4];
        float rs[4];
#pragma unroll
        for (int i = 0; i < 4; i++) {
            rs[i] = 0.f;
#pragma unroll
            for (int j = 0; j < 4; j++) acc[i][j] = 0.f;
        }

#pragma unroll 4
        for (int j = 0; j < CHUNK; j++) {
            float4 vv = *(const float4*)&V[j * SP + m0];
            float va[4] = {vv.x, vv.y, vv.z, vv.w};
#pragma unroll
            for (int ii = 0; ii < 4; ii++) {
                float sv = S[(i0 + ii) * SP + j];
                rs[ii] += sv;
#pragma unroll
                for (int mm = 0; mm < 4; mm++) acc[ii][mm] += sv * va[mm];
            }
        }
#pragma unroll 4
        for (int d = 0; d < HD; d++) {
            float4 q0 = *(const float4*)&Qt[d * SP + i0];
            float qa[4] = {q0.x, q0.y, q0.z, q0.w};
            float4 kv = *(const float4*)&KVp[d * SP + m0];
            float ka[4] = {kv.x, kv.y, kv.z, kv.w};
            float kss = ksum[d];
#pragma unroll
            for (int ii = 0; ii < 4; ii++) {
                rs[ii] += qa[ii] * kss;
#pragma unroll
                for (int mm = 0; mm < 4; mm++) acc[ii][mm] += qa[ii] * ka[mm];
            }
        }
        if (tx == 0) {
#pragma unroll
            for (int ii = 0; ii < 4; ii++) dn[i0 + ii] = rs[ii];
        }
        __syncthreads();
#pragma unroll
        for (int ii = 0; ii < 4; ii++) {
            float inv = 1.f / fmaxf(dn[i0 + ii], 1e-6f);
            size_t g = (nbase + i0 + ii) * D + h * HD + m0;
            uint16_t hh[4], ll[4];
#pragma unroll
            for (int mm = 0; mm < 4; mm++)
                split2(acc[ii][mm] * inv, hh[mm], ll[mm]);
            *(uint2*)&g_phi[g] = make_uint2((uint32_t)hh[0] | ((uint32_t)hh[1] << 16),
                                            (uint32_t)hh[2] | ((uint32_t)hh[3] << 16));
            *(uint2*)&g_plo[g] = make_uint2((uint32_t)ll[0] | ((uint32_t)ll[1] << 16),
                                            (uint32_t)ll[2] | ((uint32_t)ll[3] << 16));
        }
    }
}

// ---------------- launch ----------------
extern "C" void kernel_launch(void* const* d_in, const int* in_sizes, int n_in,
                              void* d_out, int out_size)
{
    const float* x  = (const float*)d_in[0];
    const float* Wq = (const float*)d_in[1];
    const float* bq = (const float*)d_in[2];
    const float* Wk = (const float*)d_in[3];
    const float* bk = (const float*)d_in[4];
    const float* Wv = (const float*)d_in[5];
    const float* bv = (const float*)d_in[6];
    const float* Wo = (const float*)d_in[7];
    const float* bo = (const float*)d_in[8];

    int N = in_sizes[0] / D;     // b * t
    int B = N / TSEQ;
    int rowTiles = N / 128;
    int n4x = N * D / 4;

    cudaFuncSetAttribute(mma_gemm,
                         cudaFuncAttributeMaxDynamicSharedMemorySize, GEMM_SMEM);
    cudaFuncSetAttribute(attn_chunk_kernel,
                         cudaFuncAttributeMaxDynamicSharedMemorySize,
                         SM2C_FLOATS * (int)sizeof(float));

    // merged split conversion: weights + x
    convert_all<<<(W4 + n4x + 255) / 256, 256>>>(x, Wq, Wk, Wv, Wo, n4x);

    // fused QKV projection (z = 0,1,2 -> q,k,v); elu+1 on q,k
    dim3 gq(D / 64, rowTiles, 3);
    mma_gemm<<<gq, 256, GEMM_SMEM>>>(0, 0, 0, bq, bk, bv, nullptr, 0x3);

    chunk_sum_kernel<<<dim3(B * NC, HEADS * 2), 256, CS_SMEM>>>();
    prefix_kernel<<<dim3(B * HEADS, 16), 256>>>();
    attn_chunk_kernel<<<dim3(B * NC, HEADS), 256,
                        SM2C_FLOATS * sizeof(float)>>>();

    // output projection from split attention output -> d_out
    dim3 go(D / 64, rowTiles, 1);
    mma_gemm<<<go, 256, GEMM_SMEM>>>(1, 3, 3, bo, bo, bo, (float*)d_out, 0x0);
}

// round 13
// speedup vs baseline: 1.4751x; 1.0526x over previous
#include <cuda_runtime.h>
#include <cuda_bf16.h>
#include <cstdint>

#define D 512
#define HEADS 8
#define HD 64
#define TSEQ 1024
#define CHUNK 64
#define NC (TSEQ / CHUNK)   // 16
#define MAXB 4

// ---------------- scratch (no allocations allowed) ----------------
__device__ float g_q[MAXB * TSEQ * D];
__device__ float g_k[MAXB * TSEQ * D];
__device__ float g_v[MAXB * TSEQ * D];
__device__ float g_ckv[MAXB * HEADS * NC * HD * HD];
__device__ float g_cks[MAXB * HEADS * NC * HD];
// bf16 split operands
__device__ __nv_bfloat16 g_whi[4 * D * D];
__device__ __nv_bfloat16 g_wlo[4 * D * D];
__device__ __nv_bfloat16 g_xhi[MAXB * TSEQ * D];
__device__ __nv_bfloat16 g_xlo[MAXB * TSEQ * D];
__device__ __nv_bfloat16 g_phi[MAXB * TSEQ * D];   // post-attention activations
__device__ __nv_bfloat16 g_plo[MAXB * TSEQ * D];

// ---------------- helpers ----------------
__device__ __forceinline__ void split2(float f, uint16_t& h, uint16_t& l) {
    __nv_bfloat16 hb = __float2bfloat16_rn(f);
    float hf = __bfloat162float(hb);
    __nv_bfloat16 lb = __float2bfloat16_rn(f - hf);
    h = __bfloat16_as_ushort(hb);
    l = __bfloat16_as_ushort(lb);
}
__device__ __forceinline__ float bf2f(uint16_t u) {
    return __bfloat162float(__ushort_as_bfloat16(u));
}

__device__ __forceinline__ void mma_bf16(float* d, const uint32_t* a, const uint32_t* b) {
    asm volatile(
        "mma.sync.aligned.m16n8k16.row.col.f32.bf16.bf16.f32 "
        "{%0,%1,%2,%3}, {%4,%5,%6,%7}, {%8,%9}, {%0,%1,%2,%3};"
        : "+f"(d[0]), "+f"(d[1]), "+f"(d[2]), "+f"(d[3])
        : "r"(a[0]), "r"(a[1]), "r"(a[2]), "r"(a[3]), "r"(b[0]), "r"(b[1]));
}

__device__ __forceinline__ uint32_t smem_u32(const void* p) {
    uint32_t a;
    asm("{ .reg .u64 t; cvta.to.shared.u64 t, %1; cvt.u32.u64 %0, t; }"
        : "=r"(a) : "l"(p));
    return a;
}
__device__ __forceinline__ void cp16(uint32_t dst, const void* src) {
    asm volatile("cp.async.cg.shared.global [%0], [%1], 16;"
                 :: "r"(dst), "l"(src));
}
#define CP_COMMIT() asm volatile("cp.async.commit_group;" ::: "memory")
#define CP_WAIT(n)  asm volatile("cp.async.wait_group %0;" :: "n"(n) : "memory")

#define LDSM4(r, addr) \
    asm volatile("ldmatrix.sync.aligned.m8n8.x4.shared.b16 {%0,%1,%2,%3}, [%4];" \
        : "=r"((r)[0]), "=r"((r)[1]), "=r"((r)[2]), "=r"((r)[3]) : "r"(addr))

// ---------------- merged conversion kernel (weights + x) ----------------
#define W4 (4 * D * D / 4)      // 262144 float4s of weights
__global__ void __launch_bounds__(256) convert_all(
    const float* __restrict__ x,
    const float* __restrict__ Wq, const float* __restrict__ Wk,
    const float* __restrict__ Wv, const float* __restrict__ Wo, int n4x)
{
    int gid = blockIdx.x * 256 + threadIdx.x;
    if (gid < W4) {
        int w = gid >> 16;
        int off = gid & 65535;
        const float* src = (w == 0) ? Wq : (w == 1) ? Wk : (w == 2) ? Wv : Wo;
        float4 v = ((const float4*)src)[off];
        float f[4] = {v.x, v.y, v.z, v.w};
        uint16_t h[4], l[4];
#pragma unroll
        for (int j = 0; j < 4; ++j) split2(f[j], h[j], l[j]);
        ((uint2*)(g_whi + (size_t)w * D * D))[off] =
            make_uint2((uint32_t)h[0] | ((uint32_t)h[1] << 16),
                       (uint32_t)h[2] | ((uint32_t)h[3] << 16));
        ((uint2*)(g_wlo + (size_t)w * D * D))[off] =
            make_uint2((uint32_t)l[0] | ((uint32_t)l[1] << 16),
                       (uint32_t)l[2] | ((uint32_t)l[3] << 16));
    } else {
        int i = gid - W4;
        if (i < n4x) {
            float4 v = ((const float4*)x)[i];
            float f[4] = {v.x, v.y, v.z, v.w};
            uint16_t h[4], l[4];
#pragma unroll
            for (int j = 0; j < 4; ++j) split2(f[j], h[j], l[j]);
            ((uint2*)g_xhi)[i] = make_uint2((uint32_t)h[0] | ((uint32_t)h[1] << 16),
                                            (uint32_t)h[2] | ((uint32_t)h[3] << 16));
            ((uint2*)g_xlo)[i] = make_uint2((uint32_t)l[0] | ((uint32_t)l[1] << 16),
                                            (uint32_t)l[2] | ((uint32_t)l[3] << 16));
        }
    }
}

// ---------------- mma.sync split-bf16 GEMM (tile 128x64, 2 CTAs/SM) ----------------
#define ROWU 36
#define ARRUA (128 * ROWU)     // 4608
#define ARRUB (64 * ROWU)      // 2304
#define BUFU (2 * ARRUA + 2 * ARRUB)   // 13824
#define GEMM_SMEM (2 * BUFU * 4)       // 110592 bytes

__device__ __forceinline__ void load_chunk_async(
    uint32_t sbB, const uint32_t* Ahi, const uint32_t* Alo,
    const uint32_t* Bhi, const uint32_t* Blo,
    int rowBase, int colBase, int k0u, int tid)
{
#pragma unroll
    for (int it = 0; it < 4; ++it) {
        int lin = tid + it * 256;          // 0..1023
        int r = lin >> 3, q = lin & 7;
        uint32_t dOff = (uint32_t)(r * ROWU + q * 4) * 4;
        cp16(sbB + dOff, Ahi + (size_t)(rowBase + r) * 256 + k0u + q * 4);
        cp16(sbB + ARRUA * 4 + dOff, Alo + (size_t)(rowBase + r) * 256 + k0u + q * 4);
    }
#pragma unroll
    for (int it = 0; it < 2; ++it) {
        int lin = tid + it * 256;          // 0..511
        int r = lin >> 3, q = lin & 7;
        uint32_t dOff = (uint32_t)(r * ROWU + q * 4) * 4;
        cp16(sbB + 2 * ARRUA * 4 + dOff, Bhi + (size_t)(colBase + r) * 256 + k0u + q * 4);
        cp16(sbB + (2 * ARRUA + ARRUB) * 4 + dOff,
             Blo + (size_t)(colBase + r) * 256 + k0u + q * 4);
    }
}

__global__ void __launch_bounds__(256, 2) mma_gemm(
    int asel, int wBase, int oselBase,
    const float* __restrict__ bias0, const float* __restrict__ bias1,
    const float* __restrict__ bias2,
    float* __restrict__ Oext, int actmask)
{
    extern __shared__ __align__(16) uint32_t smu[];
    int tid = threadIdx.x, lane = tid & 31, wid = tid >> 5;
    int warpRow = wid >> 2;    // 0..1 (64 rows each)
    int warpCol = wid & 3;     // 0..3 (16 cols each)
    int z = blockIdx.z;
    int rowBase = blockIdx.y * 128;
    int colBase = blockIdx.x * 64;

    const uint32_t* Ahi = asel ? (const uint32_t*)g_phi : (const uint32_t*)g_xhi;
    const uint32_t* Alo = asel ? (const uint32_t*)g_plo : (const uint32_t*)g_xlo;
    int wz = wBase + z;
    const uint32_t* Bhi = (const uint32_t*)g_whi + (size_t)wz * (D * D / 2);
    const uint32_t* Blo = (const uint32_t*)g_wlo + (size_t)wz * (D * D / 2);
    const float* bias = (z == 0) ? bias0 : (z == 1) ? bias1 : bias2;
    int osel = oselBase + z;
    float* O = (osel == 3) ? Oext : (osel == 0 ? g_q : (osel == 1 ? g_k : g_v));
    int act = (actmask >> z) & 1;

    uint32_t sbB = smem_u32(smu);

    int lrA = lane & 15, lhA = lane >> 4;
    int brB = ((lane >> 4) << 3) + (lane & 7);
    int bhB = (lane >> 3) & 1;

    float acc[4][2][4];
#pragma unroll
    for (int mt = 0; mt < 4; ++mt)
#pragma unroll
        for (int nt = 0; nt < 2; ++nt)
#pragma unroll
            for (int r = 0; r < 4; ++r) acc[mt][nt][r] = 0.f;

    load_chunk_async(sbB, Ahi, Alo, Bhi, Blo, rowBase, colBase, 0, tid);
    CP_COMMIT();

    for (int c = 0; c < 8; ++c) {
        int buf = c & 1;
        if (c < 7) {
            load_chunk_async(sbB + ((c + 1) & 1) * BUFU * 4,
                             Ahi, Alo, Bhi, Blo, rowBase, colBase,
                             (c + 1) * 32, tid);
            CP_COMMIT();
            CP_WAIT(1);
        } else {
            CP_WAIT(0);
        }
        __syncthreads();

        uint32_t aBH = sbB + (uint32_t)buf * BUFU * 4;
        uint32_t aBL = aBH + ARRUA * 4;
        uint32_t bBH = aBH + 2 * ARRUA * 4;
        uint32_t bBL = aBH + (2 * ARRUA + ARRUB) * 4;
#pragma unroll
        for (int ks = 0; ks < 4; ++ks) {
            uint32_t ahi[4][4], alo[4][4];
#pragma unroll
            for (int mt = 0; mt < 4; ++mt) {
                uint32_t off = (uint32_t)((warpRow * 64 + mt * 16 + lrA) * ROWU
                                          + ks * 8 + lhA * 4) * 4;
                LDSM4(ahi[mt], aBH + off);
                LDSM4(alo[mt], aBL + off);
            }
            uint32_t off = (uint32_t)((warpCol * 16 + brB) * ROWU
                                      + ks * 8 + bhB * 4) * 4;
            uint32_t t0[4], t1[4];
            LDSM4(t0, bBH + off);
            LDSM4(t1, bBL + off);
#pragma unroll
            for (int mt = 0; mt < 4; ++mt)
#pragma unroll
                for (int q = 0; q < 2; ++q) {
                    mma_bf16(acc[mt][q], ahi[mt], &t0[2 * q]);
                    mma_bf16(acc[mt][q], ahi[mt], &t1[2 * q]);
                    mma_bf16(acc[mt][q], alo[mt], &t0[2 * q]);
                }
        }
        __syncthreads();
    }

#pragma unroll
    for (int mt = 0; mt < 4; ++mt) {
        int r0 = rowBase + warpRow * 64 + mt * 16 + (lane >> 2);
#pragma unroll
        for (int nt = 0; nt < 2; ++nt) {
            int cc = colBase + warpCol * 16 + nt * 8 + (lane & 3) * 2;
            float b0 = bias[cc], b1 = bias[cc + 1];
            float v0 = acc[mt][nt][0] + b0;
            float v1 = acc[mt][nt][1] + b1;
            float v2 = acc[mt][nt][2] + b0;
            float v3 = acc[mt][nt][3] + b1;
            if (act) {
                v0 = (v0 > 0.f) ? v0 + 1.f : __expf(v0);
                v1 = (v1 > 0.f) ? v1 + 1.f : __expf(v1);
                v2 = (v2 > 0.f) ? v2 + 1.f : __expf(v2);
                v3 = (v3 > 0.f) ? v3 + 1.f : __expf(v3);
            }
            *(float2*)&O[(size_t)r0 * D + cc] = make_float2(v0, v1);
            *(float2*)&O[(size_t)(r0 + 8) * D + cc] = make_float2(v2, v3);
        }
    }
}

// ---------------- per-chunk local sums (CHUNK=64, m-split x2) ----------------
__global__ void __launch_bounds__(256) chunk_sum_kernel()
{
    int bc = blockIdx.x;            // b*NC + c
    int hm = blockIdx.y;
    int h = hm >> 1, mh = hm & 1;
    int b = bc / NC, c = bc % NC;
    extern __shared__ __align__(16) float smf[];
    float* ks = smf;                   // [CHUNK][HD]
    float* vs = smf + CHUNK * HD;      // [CHUNK][32]

    int tid = threadIdx.x;
    size_t nbase = (size_t)b * TSEQ + (size_t)c * CHUNK;

#pragma unroll
    for (int it = 0; it < 4; it++) {
        int lin = tid + it * 256;
        int t = lin >> 4;
        int d4 = lin & 15;
        ((float4*)ks)[lin] = *(const float4*)&g_k[(nbase + t) * D + h * HD + d4 * 4];
    }
#pragma unroll
    for (int it = 0; it < 2; it++) {
        int lin = tid + it * 256;
        int t = lin >> 3;
        int m4 = lin & 7;
        ((float4*)vs)[lin] =
            *(const float4*)&g_v[(nbase + t) * D + h * HD + mh * 32 + m4 * 4];
    }
    __syncthreads();

    int d0 = (tid >> 4) * 4;
    int m0 = (tid & 15) * 2;
    float acc[4][2];
#pragma unroll
    for (int i = 0; i < 4; i++) { acc[i][0] = 0.f; acc[i][1] = 0.f; }

#pragma unroll 8
    for (int t = 0; t < CHUNK; t++) {
        float4 kd = *(const float4*)&ks[t * HD + d0];
        float2 vm = *(const float2*)&vs[t * 32 + m0];
        float ka[4] = {kd.x, kd.y, kd.z, kd.w};
#pragma unroll
        for (int i = 0; i < 4; i++) {
            acc[i][0] += ka[i] * vm.x;
            acc[i][1] += ka[i] * vm.y;
        }
    }

    size_t sidx = ((size_t)(b * HEADS + h) * NC + c);
    float* ckv = g_ckv + sidx * HD * HD;
#pragma unroll
    for (int i = 0; i < 4; i++)
        *(float2*)&ckv[(d0 + i) * HD + mh * 32 + m0] = make_float2(acc[i][0], acc[i][1]);

    if (mh == 0 && tid < HD) {
        float s = 0.f;
#pragma unroll 8
        for (int t = 0; t < CHUNK; t++) s += ks[t * HD + tid];
        g_cks[sidx * HD + tid] = s;
    }
}
#define CS_SMEM ((CHUNK * HD + CHUNK * 32) * 4)   // 24576 B

// ---------------- exclusive prefix over chunks per (b,h) ----------------
__global__ void __launch_bounds__(256) prefix_kernel()
{
    int bh = blockIdx.x;
    int e = blockIdx.y * 256 + threadIdx.x;    // 0..4095
    float* base = g_ckv + (size_t)bh * NC * HD * HD + e;

    float v[NC];
#pragma unroll
    for (int c = 0; c < NC; c++) v[c] = base[c * HD * HD];
    float carry = 0.f;
#pragma unroll
    for (int c = 0; c < NC; c++) {
        float t = v[c];
        base[c * HD * HD] = carry;
        carry += t;
    }

    if (blockIdx.y == 0 && threadIdx.x < HD) {
        float* kb = g_cks + (size_t)bh * NC * HD + threadIdx.x;
        float w[NC];
#pragma unroll
        for (int c = 0; c < NC; c++) w[c] = kb[c * HD];
        float kc = 0.f;
#pragma unroll
        for (int c = 0; c < NC; c++) {
            float t = w[c];
            kb[c * HD] = kc;
            kc += t;
        }
    }
}

// ---------------- tensor-core per-chunk attention (CHUNK=64) ----------------
// Split-bf16 smem arrays, stride 36 u32 (72 bf16) rows, 64 rows each.
#define QHI_O 0
#define QLO_O 2304
#define KHI_O 4608
#define KLO_O 6912
#define VTHI_O 9216
#define VTLO_O 11520
#define PTHI_O 13824
#define PTLO_O 16128
#define SHI_O 18432
#define SLO_O 20736
#define KSUM_O 23040
#define DNS_O 23104
#define DNV_O 23232
#define ATTN_U32 23296
#define ATTN_SMEM (ATTN_U32 * 4)   // 93184 B -> 2 CTAs/SM

__global__ void __launch_bounds__(256) attn_chunk_kernel()
{
    int bc = blockIdx.x;
    int h = blockIdx.y;
    int b = bc / NC, c = bc % NC;
    extern __shared__ __align__(16) uint32_t smu[];
    uint16_t* sh = (uint16_t*)smu;
    float* ksum = (float*)(smu + KSUM_O);
    float* dnS = (float*)(smu + DNS_O);
    float* dnv = (float*)(smu + DNV_O);

    int tid = threadIdx.x, lane = tid & 31, wid = tid >> 5;
    size_t nbase = (size_t)b * TSEQ + (size_t)c * CHUNK;
    size_t sidx = ((size_t)(b * HEADS + h) * NC + c);
    uint32_t sbB = smem_u32(smu);

    // ---- load + split-convert Q, K, V^T, KVp^T ----
#pragma unroll
    for (int it = 0; it < 16; it++) {
        int e = tid + it * 256;        // 0..4095
        int i = e >> 6, d = e & 63;
        uint16_t hh, ll;
        float qv = g_q[(nbase + i) * D + h * HD + d];
        split2(qv, hh, ll);
        sh[QHI_O * 2 + i * 72 + d] = hh;
        sh[QLO_O * 2 + i * 72 + d] = ll;
        float kv = g_k[(nbase + i) * D + h * HD + d];
        split2(kv, hh, ll);
        sh[KHI_O * 2 + i * 72 + d] = hh;
        sh[KLO_O * 2 + i * 72 + d] = ll;
        float vv = g_v[(nbase + i) * D + h * HD + d];
        split2(vv, hh, ll);          // Vt[m=d][j=i]
        sh[VTHI_O * 2 + d * 72 + i] = hh;
        sh[VTLO_O * 2 + d * 72 + i] = ll;
        float pv = g_ckv[sidx * (HD * HD) + e];   // e = d*64+m
        split2(pv, hh, ll);          // PT[m][d]
        sh[PTHI_O * 2 + (e & 63) * 72 + (e >> 6)] = hh;
        sh[PTLO_O * 2 + (e & 63) * 72 + (e >> 6)] = ll;
    }
    if (tid < HD) ksum[tid] = g_cks[sidx * HD + tid];
    __syncthreads();

    int wr = wid >> 1, wc = wid & 1;
    int r0 = wr * 16, c0 = wc * 32;
    int lrA = lane & 15, lhA = lane >> 4;
    int brB = ((lane >> 4) << 3) + (lane & 7);
    int bhB = (lane >> 3) & 1;
    int ra = r0 + (lane >> 2), rb = ra + 8;

    // ---- stage 1: S = Q K^T (split mma), mask, rowsum, split-store ----
    {
        float s1[4][4];
#pragma unroll
        for (int nt = 0; nt < 4; ++nt)
#pragma unroll
            for (int r = 0; r < 4; ++r) s1[nt][r] = 0.f;

#pragma unroll
        for (int ksx = 0; ksx < 4; ++ksx) {
            uint32_t ahi[4], alo[4];
            uint32_t aoff = (uint32_t)((r0 + lrA) * 36 + ksx * 8 + lhA * 4) * 4;
            LDSM4(ahi, sbB + QHI_O * 4 + aoff);
            LDSM4(alo, sbB + QLO_O * 4 + aoff);
#pragma unroll
            for (int p = 0; p < 2; ++p) {
                uint32_t boff = (uint32_t)((c0 + p * 16 + brB) * 36 + ksx * 8 + bhB * 4) * 4;
                uint32_t t0[4], t1[4];
                LDSM4(t0, sbB + KHI_O * 4 + boff);
                LDSM4(t1, sbB + KLO_O * 4 + boff);
#pragma unroll
                for (int q = 0; q < 2; ++q) {
                    mma_bf16(s1[2 * p + q], ahi, &t0[2 * q]);
                    mma_bf16(s1[2 * p + q], ahi, &t1[2 * q]);
                    mma_bf16(s1[2 * p + q], alo, &t0[2 * q]);
                }
            }
        }
        float rsa = 0.f, rsb = 0.f;
#pragma unroll
        for (int nt = 0; nt < 4; ++nt) {
            int ca = c0 + nt * 8 + 2 * (lane & 3);
            float v0 = (ca <= ra) ? s1[nt][0] : 0.f;
            float v1 = (ca + 1 <= ra) ? s1[nt][1] : 0.f;
            float v2 = (ca <= rb) ? s1[nt][2] : 0.f;
            float v3 = (ca + 1 <= rb) ? s1[nt][3] : 0.f;
            rsa += v0 + v1;
            rsb += v2 + v3;
            uint16_t h0, l0, h1, l1;
            split2(v0, h0, l0); split2(v1, h1, l1);
            smu[SHI_O + ra * 36 + (ca >> 1)] = (uint32_t)h0 | ((uint32_t)h1 << 16);
            smu[SLO_O + ra * 36 + (ca >> 1)] = (uint32_t)l0 | ((uint32_t)l1 << 16);
            split2(v2, h0, l0); split2(v3, h1, l1);
            smu[SHI_O + rb * 36 + (ca >> 1)] = (uint32_t)h0 | ((uint32_t)h1 << 16);
            smu[SLO_O + rb * 36 + (ca >> 1)] = (uint32_t)l0 | ((uint32_t)l1 << 16);
        }
        rsa += __shfl_xor_sync(0xffffffff, rsa, 1);
        rsa += __shfl_xor_sync(0xffffffff, rsa, 2);
        rsb += __shfl_xor_sync(0xffffffff, rsb, 1);
        rsb += __shfl_xor_sync(0xffffffff, rsb, 2);
        if ((lane & 3) == 0) {
            dnS[ra * 2 + wc] = rsa;
            dnS[rb * 2 + wc] = rsb;
        }
    }
    __syncthreads();

    // ---- stage 2: out = S V + Q KVp (one accumulator chain) ----
    float s2[4][4];
#pragma unroll
    for (int nt = 0; nt < 4; ++nt)
#pragma unroll
        for (int r = 0; r < 4; ++r) s2[nt][r] = 0.f;

#pragma unroll
    for (int ksx = 0; ksx < 4; ++ksx) {     // S * V  (k = j)
        uint32_t ahi[4], alo[4];
        uint32_t aoff = (uint32_t)((r0 + lrA) * 36 + ksx * 8 + lhA * 4) * 4;
        LDSM4(ahi, sbB + SHI_O * 4 + aoff);
        LDSM4(alo, sbB + SLO_O * 4 + aoff);
#pragma unroll
        for (int p = 0; p < 2; ++p) {
            uint32_t boff = (uint32_t)((c0 + p * 16 + brB) * 36 + ksx * 8 + bhB * 4) * 4;
            uint32_t t0[4], t1[4];
            LDSM4(t0, sbB + VTHI_O * 4 + boff);
            LDSM4(t1, sbB + VTLO_O * 4 + boff);
#pragma unroll
            for (int q = 0; q < 2; ++q) {
                mma_bf16(s2[2 * p + q], ahi, &t0[2 * q]);
                mma_bf16(s2[2 * p + q], ahi, &t1[2 * q]);
                mma_bf16(s2[2 * p + q], alo, &t0[2 * q]);
            }
        }
    }
#pragma unroll
    for (int ksx = 0; ksx < 4; ++ksx) {     // Q * KVp  (k = d)
        uint32_t ahi[4], alo[4];
        uint32_t aoff = (uint32_t)((r0 + lrA) * 36 + ksx * 8 + lhA * 4) * 4;
        LDSM4(ahi, sbB + QHI_O * 4 + aoff);
        LDSM4(alo, sbB + QLO_O * 4 + aoff);
#pragma unroll
        for (int p = 0; p < 2; ++p) {
            uint32_t boff = (uint32_t)((c0 + p * 16 + brB) * 36 + ksx * 8 + bhB * 4) * 4;
            uint32_t t0[4], t1[4];
            LDSM4(t0, sbB + PTHI_O * 4 + boff);
            LDSM4(t1, sbB + PTLO_O * 4 + boff);
#pragma unroll
            for (int q = 0; q < 2; ++q) {
                mma_bf16(s2[2 * p + q], ahi, &t0[2 * q]);
                mma_bf16(s2[2 * p + q], ahi, &t1[2 * q]);
                mma_bf16(s2[2 * p + q], alo, &t0[2 * q]);
            }
        }
    }

    // ---- denom: rowsum(maskS) + Q . ksum ----
    if (tid < 64) {
        float s = dnS[tid * 2] + dnS[tid * 2 + 1];
#pragma unroll 8
        for (int d = 0; d < HD; ++d) {
            float qv = bf2f(sh[QHI_O * 2 + tid * 72 + d]) +
                       bf2f(sh[QLO_O * 2 + tid * 72 + d]);
            s += qv * ksum[d];
        }
        dnv[tid] = 1.f / fmaxf(s, 1e-6f);
    }
    __syncthreads();

    // ---- epilogue: scale + split-store ----
    float ia = dnv[ra], ib = dnv[rb];
#pragma unroll
    for (int nt = 0; nt < 4; ++nt) {
        int ca = c0 + nt * 8 + 2 * (lane & 3);
        float o0 = s2[nt][0] * ia;
        float o1 = s2[nt][1] * ia;
        float o2 = s2[nt][2] * ib;
        float o3 = s2[nt][3] * ib;
        uint16_t h0, l0, h1, l1;
        size_t ga = (nbase + ra) * D + h * HD + ca;
        size_t gb = (nbase + rb) * D + h * HD + ca;
        split2(o0, h0, l0); split2(o1, h1, l1);
        *(uint32_t*)&g_phi[ga] = (uint32_t)h0 | ((uint32_t)h1 << 16);
        *(uint32_t*)&g_plo[ga] = (uint32_t)l0 | ((uint32_t)l1 << 16);
        split2(o2, h0, l0); split2(o3, h1, l1);
        *(uint32_t*)&g_phi[gb] = (uint32_t)h0 | ((uint32_t)h1 << 16);
        *(uint32_t*)&g_plo[gb] = (uint32_t)l0 | ((uint32_t)l1 << 16);
    }
}

// ---------------- launch ----------------
extern "C" void kernel_launch(void* const* d_in, const int* in_sizes, int n_in,
                              void* d_out, int out_size)
{
    const float* x  = (const float*)d_in[0];
    const float* Wq = (const float*)d_in[1];
    const float* bq = (const float*)d_in[2];
    const float* Wk = (const float*)d_in[3];
    const float* bk = (const float*)d_in[4];
    const float* Wv = (const float*)d_in[5];
    const float* bv = (const float*)d_in[6];
    const float* Wo = (const float*)d_in[7];
    const float* bo = (const float*)d_in[8];

    int N = in_sizes[0] / D;     // b * t
    int B = N / TSEQ;
    int rowTiles = N / 128;
    int n4x = N * D / 4;

    cudaFuncSetAttribute(mma_gemm,
                         cudaFuncAttributeMaxDynamicSharedMemorySize, GEMM_SMEM);
    cudaFuncSetAttribute(attn_chunk_kernel,
                         cudaFuncAttributeMaxDynamicSharedMemorySize, ATTN_SMEM);

    // merged split conversion: weights + x
    convert_all<<<(W4 + n4x + 255) / 256, 256>>>(x, Wq, Wk, Wv, Wo, n4x);

    // fused QKV projection (z = 0,1,2 -> q,k,v); elu+1 on q,k
    dim3 gq(D / 64, rowTiles, 3);
    mma_gemm<<<gq, 256, GEMM_SMEM>>>(0, 0, 0, bq, bk, bv, nullptr, 0x3);

    chunk_sum_kernel<<<dim3(B * NC, HEADS * 2), 256, CS_SMEM>>>();
    prefix_kernel<<<dim3(B * HEADS, 16), 256>>>();
    attn_chunk_kernel<<<dim3(B * NC, HEADS), 256, ATTN_SMEM>>>();

    // output projection from split attention output -> d_out
    dim3 go(D / 64, rowTiles, 1);
    mma_gemm<<<go, 256, GEMM_SMEM>>>(1, 3, 3, bo, bo, bo, (float*)d_out, 0x0);
}